// round 8
// baseline (speedup 1.0000x reference)
#include <cuda_runtime.h>

#define N_SAMPLES 65536
#define TPB 256
#define EPT 16
#define TILE (TPB * EPT)            // 4096 samples per block
#define CHUNKS (N_SAMPLES / TILE)   // 16 blocks per row
#define MAXB 512

#define TWOPI_F 6.28318530717958647692f   /* fl32(2*pi) */
#define INV2PI_D 0.15915494309189533576888376337251

struct Row {
    float2 base_t, p0_t;          // carrier slope/phase (turns, DS)
    float2 dfm_t, pfm_t;          // fm slope/phase (turns, DS)
    float2 hd_t;                  // dfm/2 (turns, DS)
    float2 mk;                    // mfm*K2/(2pi) (turns, DS)
    float  cosc2;                 // cos(c2)
    float  basef, mfmf, fmt16;    // carrier/fm-depth/16*dfm (rad)
    float  amt_turns, pam_turns, am16, hmiam;
};
__device__ Row g_rows[MAXB];

__device__ __forceinline__ float2 ds_from_d(double x) {
    float h = (float)x;
    return make_float2(h, (float)(x - (double)h));
}

// ---- setup: one row per LANE, all chains SIMT (no divergence).
// All FP64 lives here: 8 blocks x 32 lanes for B=256.
__global__ void setup_kernel(const float* __restrict__ theta_am,
                             const float* __restrict__ theta_fm,
                             const float* __restrict__ phase,
                             const float* __restrict__ phase_am,
                             const float* __restrict__ phase_fm,
                             const float* __restrict__ u_am_mi,
                             const float* __restrict__ u_fm_hz,
                             const float* __restrict__ u_f0_hz,
                             int B)
{
    const int row = blockIdx.x * 32 + threadIdx.x;
    if (row >= B) return;
    const double INV_SR = 1.0 / 44100.0;
    Row* r = &g_rows[row];

    // carrier chain
    const double lgl = log2(32.7);
    const double lgh = log2(523.25);
    float x0 = __fadd_rn(__fmul_rn(u_f0_hz[row], (float)(lgh - lgl)), (float)lgl);
    float f0_hz = (float)exp2((double)x0);
    double base = (double)__fmul_rn(TWOPI_F, f0_hz) * INV_SR;   // rad/sample
    double mfm  = base * (double)theta_fm[row];                 // rad/sample
    r->base_t = ds_from_d(base * INV2PI_D);
    r->p0_t   = ds_from_d((double)__fmul_rn(TWOPI_F, phase[row]) * INV2PI_D);
    r->basef  = (float)base;
    r->mfmf   = (float)mfm;

    // fm chain
    float xf = __fadd_rn(__fmul_rn(u_fm_hz[row], 4.0f), -1.0f);
    float fm_hz = (float)exp2((double)xf);
    double dfm = (double)__fmul_rn(TWOPI_F, fm_hz) * INV_SR;    // rad/sample
    double half = 0.5 * dfm;
    double K2 = 0.5 / sin(half);
    double pfm = (double)__fmul_rn(TWOPI_F, phase_fm[row]);
    double c2  = pfm - half;
    r->dfm_t = ds_from_d(dfm * INV2PI_D);
    r->pfm_t = ds_from_d(pfm * INV2PI_D);
    r->hd_t  = ds_from_d(half * INV2PI_D);
    r->mk    = ds_from_d(mfm * K2 * INV2PI_D);
    r->cosc2 = (float)cos(c2);
    r->fmt16 = (float)(16.0 * dfm);

    // am chain
    float xa = __fadd_rn(__fmul_rn(theta_am[row], 4.0f), -1.0f);
    float am_hz = (float)exp2((double)xa);
    double am_rad = (double)__fmul_rn(TWOPI_F, am_hz) * INV_SR;
    r->amt_turns = (float)(am_rad * INV2PI_D);
    r->pam_turns = (float)((double)__fmul_rn(TWOPI_F, phase_am[row]) * INV2PI_D);
    r->am16  = (float)(16.0 * am_rad);
    r->hmiam = 0.5f * u_am_mi[row];
}

// frac(c*n + p) in turns via double-single fp32 arithmetic.
__device__ __forceinline__ float2 ds_anchor(float2 c, float2 p, float n) {
    float ph = __fmul_rn(c.x, n);
    float pe = fmaf(c.x, n, -ph);            // exact twoProd residual
    float pl = fmaf(c.y, n, pe);
    float s  = ph + p.x;                     // two-sum
    float bb = s - ph;
    float er = (ph - (s - bb)) + (p.x - bb);
    float lo = er + pl + p.y;
    float q  = rintf(s);
    float rh = s - q;                        // exact
    float t  = rh + lo;
    float tl = lo - (t - rh);
    return make_float2(t, tl);
}

// cos(2*pi*(x.hi+x.lo)) for |x.hi| <= 0.5+eps; abs err ~1.2e-7
__device__ __forceinline__ float cos2pi(float2 x) {
    float k = rintf(2.0f * x.x);
    float z = (x.x - 0.5f * k) + x.y;
    float u = z * z;
    float pp = fmaf(7.9033069f, u, -26.4262561f);
    pp = fmaf(pp, u,  60.2446416f);
    pp = fmaf(pp, u, -85.4568172f);
    pp = fmaf(pp, u,  64.9393940f);
    pp = fmaf(pp, u, -19.7392088f);
    float c = fmaf(pp, u, 1.0f);
    float sgn = fmaf(-2.0f, fabsf(k), 1.0f);
    return c * sgn;
}

// XOR swizzle at float4 granularity (conflict-free both phases)
__device__ __forceinline__ int sw(int v) { return v ^ ((v >> 3) & 7); }

__global__ __launch_bounds__(TPB, 6)
void amfm_main(float* __restrict__ out)
{
    __shared__ float4 tile4[TILE / 4];       // 16 KB

    const int bx    = blockIdx.x;
    const int row   = bx >> 4;               // / CHUNKS
    const int chunk = bx & (CHUNKS - 1);
    const int tid   = threadIdx.x;

    const Row* __restrict__ rp = &g_rows[row];
    const float2 base_t = rp->base_t, p0_t = rp->p0_t;
    const float2 dfm_t = rp->dfm_t, pfm_t = rp->pfm_t, hd_t = rp->hd_t;
    const float2 mk = rp->mk;
    const float cosc2 = rp->cosc2;
    const float basef = rp->basef, mfmf = rp->mfmf, fmt16 = rp->fmt16;
    const float amt_turns = rp->amt_turns, pam_turns = rp->pam_turns,
                am16 = rp->am16, hmiam = rp->hmiam;

    const float n = (float)(chunk * TILE + tid * EPT);   // exact integer

    // ---- fm phase anchor (DS, turns): ftt = frac(dfm*n + pfm) ----
    float2 ftt = ds_anchor(dfm_t, pfm_t, n);

    // ---- th = ftt - hd  (DS subtract; th is the cos argument n*dfm + c2) ----
    float sh = ftt.x - hd_t.x;
    float sb = sh - ftt.x;
    float se = (ftt.x - (sh - sb)) - (hd_t.x + sb);
    float sl = se + (ftt.y - hd_t.y);
    float cth = cos2pi(make_float2(sh, sl));

    // ---- modulation: mod = mk * (cosc2 - cth)  (DS) ----
    float d  = cosc2 - cth;                  // twoDiff
    float db = d - cosc2;
    float de = (cosc2 - (d - db)) - (cth + db);
    float mh = __fmul_rn(mk.x, d);
    float ml = fmaf(mk.x, d, -mh) + fmaf(mk.y, d, __fmul_rn(mk.x, de));

    // ---- carrier anchor: frac(base*n + p0 + mod), to radians ----
    float gh = __fmul_rn(base_t.x, n);
    float ge = fmaf(base_t.x, n, -gh);
    float gl = fmaf(base_t.y, n, ge);
    float s1 = gh + p0_t.x;
    float b1 = s1 - gh;
    float e1 = (gh - (s1 - b1)) + (p0_t.x - b1);
    float s2 = s1 + mh;
    float b2 = s2 - s1;
    float e2 = (s1 - (s2 - b2)) + (mh - b2);
    float lo = gl + p0_t.y + e1 + ml + e2;
    float q  = rintf(s2);
    float s  = TWOPI_F * ((s2 - q) + lo);    // carrier phase (rad), |s|<=~3.2

    // ---- fm modulator endpoints -> quadratic phase track (2nd differences) ----
    float ft   = TWOPI_F * (ftt.x + ftt.y);
    float sf0  = __sinf(ft);
    float sf16 = __sinf(ft + fmt16);
    float d1s  = fmaf(mfmf, sf0, basef);                    // inc at k=0
    float d2s  = (fmaf(mfmf, sf16, basef) - d1s) * 0.0625f; // slope/16

    // ---- am modulator endpoints -> linear envelope ----
    float ap   = fmaf(amt_turns, n, pam_turns);
    float ar   = TWOPI_F * (ap - rintf(ap));
    float sa0  = __sinf(ar);
    float sa16 = __sinf(ar + am16);
    float w    = fmaf(hmiam, sa0, 0.5f);
    float dw   = (fmaf(hmiam, sa16, 0.5f) - w) * 0.0625f;

    // ---- synthesize 16 samples: 4 fp32 + 1 MUFU per sample ----
    #pragma unroll
    for (int g = 0; g < 4; g++) {
        float v[4];
        #pragma unroll
        for (int j = 0; j < 4; j++) {
            s += d1s;  d1s += d2s;           // quadratic phase
            float xc = __sinf(s);            // carrier
            v[j] = xc * w;  w += dw;         // linear AM envelope
        }
        tile4[sw(4 * tid + g)] = make_float4(v[0], v[1], v[2], v[3]);
    }
    __syncthreads();

    // ---- coalesced writeback: warp writes 512B contiguous per STG.128 ----
    float4* __restrict__ o4 =
        (float4*)(out + (size_t)row * N_SAMPLES + chunk * TILE);
    #pragma unroll
    for (int r = 0; r < 4; r++) {
        o4[r * 256 + tid] = tile4[sw(r * 256 + tid)];
    }
}

extern "C" void kernel_launch(void* const* d_in, const int* in_sizes, int n_in,
                              void* d_out, int out_size) {
    const int B = in_sizes[0];   // 256 rows
    setup_kernel<<<(B + 31) / 32, 32>>>(
        (const float*)d_in[0],   // theta_am_0to1
        (const float*)d_in[1],   // theta_fm_0to1
        (const float*)d_in[2],   // phase
        (const float*)d_in[3],   // phase_am
        (const float*)d_in[4],   // phase_fm
        (const float*)d_in[5],   // u_am_mi
        (const float*)d_in[6],   // u_fm_hz
        (const float*)d_in[7],   // u_f0_hz
        B);
    amfm_main<<<B * CHUNKS, TPB>>>((float*)d_out);
}

// round 9
// speedup vs baseline: 1.2076x; 1.2076x over previous
#include <cuda_runtime.h>

#define N_SAMPLES 65536
#define TPB 256
#define EPT 16
#define TILE (TPB * EPT)            // 4096 samples per block
#define CHUNKS (N_SAMPLES / TILE)   // 16 blocks per row
#define MAXB 512

#define TWOPI_F 6.28318530717958647692f   /* fl32(2*pi) */
#define INV2PI_D 0.15915494309189533576888376337251

struct Row {
    float2 base_t, p0_t;          // carrier slope/phase (turns, DS)
    float2 dfm_t, pfm_t, hd_t;    // fm slope/phase/half-slope (turns, DS)
    float2 mfm_t;                 // fm depth (rad/sample, DS)   [carrier chain]
    float2 k2t_t;                 // K2/(2pi) (DS)               [fm chain]
    float  cosc2;                 // cos(c2)
    float  basef, mfmf, fmt16;    // rad/sample fp32, 16*dfm rad
    float  amt_turns, pam_turns, am16, hmiam;
};
__device__ Row g_rows[MAXB];

__device__ __forceinline__ float2 ds_from_d(double x) {
    float h = (float)x;
    return make_float2(h, (float)(x - (double)h));
}

// exp2(x), |x| <= ~10, rel err ~1e-14 (deg-11 Taylor in ln2*f + exact 2^k)
__device__ __forceinline__ double exp2d(double x) {
    double k = rint(x);
    double f = x - k;                         // |f| <= 0.5, exact
    double p = 4.4455382718708125e-10;        // ln2^11/11!
    p = fma(p, f, 7.0549116208011210e-09);
    p = fma(p, f, 1.0178086009239699e-07);
    p = fma(p, f, 1.3215486790144307e-06);
    p = fma(p, f, 1.5252733804059837e-05);
    p = fma(p, f, 1.5403530393381629e-04);
    p = fma(p, f, 1.3333558146428443e-03);
    p = fma(p, f, 9.6181291076284772e-03);
    p = fma(p, f, 5.5504108664821580e-02);
    p = fma(p, f, 2.4022650695910071e-01);
    p = fma(p, f, 6.9314718055994531e-01);
    p = fma(p, f, 1.0);
    long long ki = (long long)k;
    return __longlong_as_double(__double_as_longlong(p) + (ki << 52));
}

// 1/x via fp32 rcp + two DP Newton steps (full DP accuracy)
__device__ __forceinline__ double drcp(double x) {
    double y = (double)__frcp_rn((float)x);
    y = y * fma(-x, y, 2.0);
    y = y * fma(-x, y, 2.0);
    return y;
}

// cos(x), |x| <= ~8, abs err ~4e-9
__device__ __forceinline__ double dcos_red(double x) {
    const double TWOPI_D = 6.283185307179586476925286766559;
    double q = rint(x * INV2PI_D);
    double r = fma(-q, TWOPI_D, x);
    double u = r * r;
    double p = -1.5619206968586225e-16;
    p = fma(p, u,  4.7794773323873853e-14);
    p = fma(p, u, -1.1470745597729725e-11);
    p = fma(p, u,  2.0876756987868098e-09);
    p = fma(p, u, -2.7557319223985893e-07);
    p = fma(p, u,  2.4801587301587302e-05);
    p = fma(p, u, -1.3888888888888889e-03);
    p = fma(p, u,  4.1666666666666664e-02);
    p = fma(p, u, -0.5);
    return fma(p, u, 1.0);
}

// ---- setup: block = (chain type, 32-row group); SIMT, short DP chains ----
__global__ void setup_kernel(const float* __restrict__ theta_am,
                             const float* __restrict__ theta_fm,
                             const float* __restrict__ phase,
                             const float* __restrict__ phase_am,
                             const float* __restrict__ phase_fm,
                             const float* __restrict__ u_am_mi,
                             const float* __restrict__ u_fm_hz,
                             const float* __restrict__ u_f0_hz,
                             int B, int groups)
{
    const int chain = blockIdx.x / groups;
    const int row   = (blockIdx.x - chain * groups) * 32 + threadIdx.x;
    if (row >= B) return;
    const double INV_SR = 1.0 / 44100.0;
    Row* r = &g_rows[row];

    if (chain == 0) {
        // AM chain (fp32-precision targets only)
        float xa = __fadd_rn(__fmul_rn(theta_am[row], 4.0f), -1.0f);
        float am_hz = (float)exp2d((double)xa);
        double am_rad = (double)__fmul_rn(TWOPI_F, am_hz) * INV_SR;
        r->amt_turns = (float)(am_rad * INV2PI_D);
        r->pam_turns = (float)((double)__fmul_rn(TWOPI_F, phase_am[row]) * INV2PI_D);
        r->am16  = (float)(16.0 * am_rad);
        r->hmiam = 0.5f * u_am_mi[row];
    } else if (chain == 1) {
        // FM chain
        float xf = __fadd_rn(__fmul_rn(u_fm_hz[row], 4.0f), -1.0f);
        float fm_hz = (float)exp2d((double)xf);
        double dfm = (double)__fmul_rn(TWOPI_F, fm_hz) * INV_SR;   // rad/sample
        double half = 0.5 * dfm;                                    // <= 5.7e-4
        double h2 = half * half;
        double sinh = half * fma(h2, fma(h2, (1.0/120.0), -(1.0/6.0)), 1.0);
        double K2 = 0.5 * drcp(sinh);
        double pfm = (double)__fmul_rn(TWOPI_F, phase_fm[row]);
        double c2  = pfm - half;
        r->dfm_t = ds_from_d(dfm * INV2PI_D);
        r->pfm_t = ds_from_d(pfm * INV2PI_D);
        r->hd_t  = ds_from_d(half * INV2PI_D);
        r->k2t_t = ds_from_d(K2 * INV2PI_D);
        r->cosc2 = (float)dcos_red(c2);
        r->fmt16 = (float)(16.0 * dfm);
    } else {
        // carrier chain (keep libm log2 for bit-exact range constants)
        double lgl = log2(32.7);
        double lgh = log2(523.25);
        float x0 = __fadd_rn(__fmul_rn(u_f0_hz[row], (float)(lgh - lgl)), (float)lgl);
        float f0_hz = (float)exp2d((double)x0);
        double base = (double)__fmul_rn(TWOPI_F, f0_hz) * INV_SR;  // rad/sample
        double mfm  = base * (double)theta_fm[row];                // rad/sample
        r->base_t = ds_from_d(base * INV2PI_D);
        r->p0_t   = ds_from_d((double)__fmul_rn(TWOPI_F, phase[row]) * INV2PI_D);
        r->mfm_t  = ds_from_d(mfm);
        r->basef  = (float)base;
        r->mfmf   = (float)mfm;
    }
}

// frac(c*n + p) in turns via double-single fp32 arithmetic.
__device__ __forceinline__ float2 ds_anchor(float2 c, float2 p, float n) {
    float ph = __fmul_rn(c.x, n);
    float pe = fmaf(c.x, n, -ph);            // exact twoProd residual
    float pl = fmaf(c.y, n, pe);
    float s  = ph + p.x;                     // two-sum
    float bb = s - ph;
    float er = (ph - (s - bb)) + (p.x - bb);
    float lo = er + pl + p.y;
    float q  = rintf(s);
    float rh = s - q;                        // exact
    float t  = rh + lo;
    float tl = lo - (t - rh);
    return make_float2(t, tl);
}

// cos(2*pi*(x.hi+x.lo)) for |x.hi| <= 0.5+eps; abs err ~1.2e-7
__device__ __forceinline__ float cos2pi(float2 x) {
    float k = rintf(2.0f * x.x);
    float z = (x.x - 0.5f * k) + x.y;
    float u = z * z;
    float pp = fmaf(7.9033069f, u, -26.4262561f);
    pp = fmaf(pp, u,  60.2446416f);
    pp = fmaf(pp, u, -85.4568172f);
    pp = fmaf(pp, u,  64.9393940f);
    pp = fmaf(pp, u, -19.7392088f);
    float c = fmaf(pp, u, 1.0f);
    float sgn = fmaf(-2.0f, fabsf(k), 1.0f);
    return c * sgn;
}

// XOR swizzle at float4 granularity (conflict-free both phases)
__device__ __forceinline__ int sw(int v) { return v ^ ((v >> 3) & 7); }

__global__ __launch_bounds__(TPB, 6)
void amfm_main(float* __restrict__ out)
{
    __shared__ float4 tile4[TILE / 4];       // 16 KB

    const int bx    = blockIdx.x;
    const int row   = bx >> 4;               // / CHUNKS
    const int chunk = bx & (CHUNKS - 1);
    const int tid   = threadIdx.x;

    const Row* __restrict__ rp = &g_rows[row];
    const float2 base_t = rp->base_t, p0_t = rp->p0_t;
    const float2 dfm_t = rp->dfm_t, pfm_t = rp->pfm_t, hd_t = rp->hd_t;
    const float2 mfm_t = rp->mfm_t, k2t_t = rp->k2t_t;
    const float cosc2 = rp->cosc2;
    const float basef = rp->basef, mfmf = rp->mfmf, fmt16 = rp->fmt16;
    const float amt_turns = rp->amt_turns, pam_turns = rp->pam_turns,
                am16 = rp->am16, hmiam = rp->hmiam;

    // mk = mfm * K2/(2pi)  (DS multiply)
    float mkh = __fmul_rn(mfm_t.x, k2t_t.x);
    float mke = fmaf(mfm_t.x, k2t_t.x, -mkh);
    float mkl = fmaf(mfm_t.x, k2t_t.y, fmaf(mfm_t.y, k2t_t.x, mke));

    const float n = (float)(chunk * TILE + tid * EPT);   // exact integer

    // ---- fm phase anchor (DS, turns): ftt = frac(dfm*n + pfm) ----
    float2 ftt = ds_anchor(dfm_t, pfm_t, n);

    // ---- th = ftt - hd  (DS subtract; cos argument n*dfm + c2) ----
    float sh = ftt.x - hd_t.x;
    float sb = sh - ftt.x;
    float se = (ftt.x - (sh - sb)) - (hd_t.x + sb);
    float sl = se + (ftt.y - hd_t.y);
    float cth = cos2pi(make_float2(sh, sl));

    // ---- modulation: mod = mk * (cosc2 - cth)  (DS) ----
    float d  = cosc2 - cth;                  // twoDiff
    float db = d - cosc2;
    float de = (cosc2 - (d - db)) - (cth + db);
    float mh = __fmul_rn(mkh, d);
    float ml = fmaf(mkh, d, -mh) + fmaf(mkl, d, __fmul_rn(mkh, de));

    // ---- carrier anchor: frac(base*n + p0 + mod), to radians ----
    float gh = __fmul_rn(base_t.x, n);
    float ge = fmaf(base_t.x, n, -gh);
    float gl = fmaf(base_t.y, n, ge);
    float s1 = gh + p0_t.x;
    float b1 = s1 - gh;
    float e1 = (gh - (s1 - b1)) + (p0_t.x - b1);
    float s2 = s1 + mh;
    float b2 = s2 - s1;
    float e2 = (s1 - (s2 - b2)) + (mh - b2);
    float lo = gl + p0_t.y + e1 + ml + e2;
    float q  = rintf(s2);
    float s  = TWOPI_F * ((s2 - q) + lo);    // carrier phase (rad)

    // ---- fm modulator endpoints -> quadratic phase track (2nd differences) ----
    float ft   = TWOPI_F * (ftt.x + ftt.y);
    float sf0  = __sinf(ft);
    float sf16 = __sinf(ft + fmt16);
    float d1s  = fmaf(mfmf, sf0, basef);                    // inc at k=0
    float d2s  = (fmaf(mfmf, sf16, basef) - d1s) * 0.0625f; // slope/16

    // ---- am modulator endpoints -> linear envelope ----
    float ap   = fmaf(amt_turns, n, pam_turns);
    float ar   = TWOPI_F * (ap - rintf(ap));
    float sa0  = __sinf(ar);
    float sa16 = __sinf(ar + am16);
    float w    = fmaf(hmiam, sa0, 0.5f);
    float dw   = (fmaf(hmiam, sa16, 0.5f) - w) * 0.0625f;

    // ---- synthesize 16 samples: 4 fp32 + 1 MUFU per sample ----
    #pragma unroll
    for (int g = 0; g < 4; g++) {
        float v[4];
        #pragma unroll
        for (int j = 0; j < 4; j++) {
            s += d1s;  d1s += d2s;           // quadratic phase
            float xc = __sinf(s);            // carrier
            v[j] = xc * w;  w += dw;         // linear AM envelope
        }
        tile4[sw(4 * tid + g)] = make_float4(v[0], v[1], v[2], v[3]);
    }
    __syncthreads();

    // ---- coalesced writeback: warp writes 512B contiguous per STG.128 ----
    float4* __restrict__ o4 =
        (float4*)(out + (size_t)row * N_SAMPLES + chunk * TILE);
    #pragma unroll
    for (int r = 0; r < 4; r++) {
        o4[r * 256 + tid] = tile4[sw(r * 256 + tid)];
    }
}

extern "C" void kernel_launch(void* const* d_in, const int* in_sizes, int n_in,
                              void* d_out, int out_size) {
    const int B = in_sizes[0];   // 256 rows
    const int groups = (B + 31) / 32;
    setup_kernel<<<3 * groups, 32>>>(
        (const float*)d_in[0],   // theta_am_0to1
        (const float*)d_in[1],   // theta_fm_0to1
        (const float*)d_in[2],   // phase
        (const float*)d_in[3],   // phase_am
        (const float*)d_in[4],   // phase_fm
        (const float*)d_in[5],   // u_am_mi
        (const float*)d_in[6],   // u_fm_hz
        (const float*)d_in[7],   // u_f0_hz
        B, groups);
    amfm_main<<<B * CHUNKS, TPB>>>((float*)d_out);
}